// round 2
// baseline (speedup 1.0000x reference)
#include <cuda_runtime.h>

#define NN 100000
#define EE 3200000
#define XDIM 256
#define HDIM 128
#define GDIM 128
#define DDIM 257

// ---------- scratch (device globals; no allocation allowed) ----------
__device__ float g_h[(size_t)NN * HDIM];    // h = (T*phi) @ W_gcn
__device__ float g_agg[(size_t)NN * GDIM];  // aggregation buffer (init: h/deg)
__device__ int   g_cnt[NN];                 // in-degree (no self loop)
__device__ float g_zsum[NN];                // sum of T[src] per dst
__device__ float g_dis[NN];                 // rsqrt(deg)

// ---------- kernel 0: zero per-launch accumulators ----------
__global__ void k_zero()
{
    int i = blockIdx.x * blockDim.x + threadIdx.x;
    if (i < NN) { g_cnt[i] = 0; g_zsum[i] = 0.f; }
}

// ---------- kernel 1: fused phi = relu(X@Wphi+b), write phi to rep,
//                      then h = (T*phi) @ Wgcn ----------
__global__ __launch_bounds__(256) void k_phi(
    const float* __restrict__ X, const float* __restrict__ T,
    const float* __restrict__ Wphi, const float* __restrict__ bphi,
    const float* __restrict__ Wgcn, float* __restrict__ out_rep)
{
    __shared__ float smem[12288]; // 48KB
    // phase 1 layout
    float* sX = smem;             // [64][33]
    float* sW = smem + 64 * 33;   // [32][128]
    // phase 2 layout (reuses whole buffer)
    float* sP  = smem;            // [64][128]  (T-scaled phi)
    float* sWg = smem + 64 * 128; // [32][128]

    const int row0 = blockIdx.x * 64;
    const int t  = threadIdx.x;
    const int ty = t >> 4, tx = t & 15;
    const int r0 = ty * 4, c0 = tx * 8;

    float acc[4][8];
#pragma unroll
    for (int i = 0; i < 4; i++)
#pragma unroll
        for (int j = 0; j < 8; j++) acc[i][j] = 0.f;

    // ---- phase 1: phi GEMM (K = 256) ----
    for (int k0 = 0; k0 < XDIM; k0 += 32) {
#pragma unroll
        for (int i = 0; i < 8; i++) {
            int idx = t + i * 256;
            int r = idx >> 5, kk = idx & 31;
            int grow = row0 + r;
            sX[r * 33 + kk] = (grow < NN) ? X[(size_t)grow * XDIM + k0 + kk] : 0.f;
        }
#pragma unroll
        for (int i = 0; i < 16; i++) {
            int idx = t + i * 256;
            int kr = idx >> 7, c = idx & 127;
            sW[kr * 128 + c] = Wphi[(size_t)(k0 + kr) * HDIM + c];
        }
        __syncthreads();
#pragma unroll
        for (int kk = 0; kk < 32; kk++) {
            float a[4], w[8];
#pragma unroll
            for (int i = 0; i < 4; i++) a[i] = sX[(r0 + i) * 33 + kk];
#pragma unroll
            for (int j = 0; j < 8; j++) w[j] = sW[kk * 128 + c0 + j];
#pragma unroll
            for (int i = 0; i < 4; i++)
#pragma unroll
                for (int j = 0; j < 8; j++) acc[i][j] = fmaf(a[i], w[j], acc[i][j]);
        }
        __syncthreads();
    }

    // ---- epilogue 1: relu + bias; write phi to rep; stash T*phi in smem ----
    float tv[4];
#pragma unroll
    for (int i = 0; i < 4; i++) {
        int grow = row0 + r0 + i;
        tv[i] = (grow < NN) ? T[grow] : 0.f;
    }
#pragma unroll
    for (int i = 0; i < 4; i++) {
        int grow = row0 + r0 + i;
#pragma unroll
        for (int j = 0; j < 8; j++) {
            float p = acc[i][j] + bphi[c0 + j];
            p = p > 0.f ? p : 0.f;
            if (grow < NN) out_rep[(size_t)grow * DDIM + c0 + j] = p;
            sP[(r0 + i) * 128 + c0 + j] = p * tv[i];
            acc[i][j] = 0.f; // reuse accumulators for phase 2
        }
    }
    __syncthreads();

    // ---- phase 2: h = (T*phi) @ Wgcn (K = 128) ----
    for (int k0 = 0; k0 < HDIM; k0 += 32) {
#pragma unroll
        for (int i = 0; i < 16; i++) {
            int idx = t + i * 256;
            int kr = idx >> 7, c = idx & 127;
            sWg[kr * 128 + c] = Wgcn[(size_t)(k0 + kr) * GDIM + c];
        }
        __syncthreads();
#pragma unroll
        for (int kk = 0; kk < 32; kk++) {
            float a[4], w[8];
#pragma unroll
            for (int i = 0; i < 4; i++) a[i] = sP[(r0 + i) * 128 + k0 + kk];
#pragma unroll
            for (int j = 0; j < 8; j++) w[j] = sWg[kk * 128 + c0 + j];
#pragma unroll
            for (int i = 0; i < 4; i++)
#pragma unroll
                for (int j = 0; j < 8; j++) acc[i][j] = fmaf(a[i], w[j], acc[i][j]);
        }
        __syncthreads();
    }
#pragma unroll
    for (int i = 0; i < 4; i++) {
        int grow = row0 + r0 + i;
        if (grow < NN)
#pragma unroll
            for (int j = 0; j < 8; j++)
                g_h[(size_t)grow * GDIM + c0 + j] = acc[i][j];
    }
}

// ---------- kernel 2: per-edge degree count + T scatter ----------
__global__ void k_edge1(const int* __restrict__ ei, const float* __restrict__ T)
{
    int e = blockIdx.x * blockDim.x + threadIdx.x;
    if (e >= EE) return;
    int s = ei[e];
    int d = ei[EE + e];
    atomicAdd(&g_cnt[d], 1);
    atomicAdd(&g_zsum[d], T[s]);
}

// ---------- kernel 3: per-node: deg, dis, z, agg init (self loop), y init ----------
__global__ void k_node(const float* __restrict__ b01, const float* __restrict__ b11,
                       float* __restrict__ y0, float* __restrict__ y1,
                       float* __restrict__ out_rep)
{
    int w = (blockIdx.x * blockDim.x + threadIdx.x) >> 5;
    int lane = threadIdx.x & 31;
    if (w >= NN) return;
    int c = g_cnt[w];
    float deg = (float)c + 1.0f;
    float invd = 1.0f / deg;
    float4 hv = *(const float4*)&g_h[(size_t)w * GDIM + lane * 4];
    float4 av = make_float4(hv.x * invd, hv.y * invd, hv.z * invd, hv.w * invd);
    *(float4*)&g_agg[(size_t)w * GDIM + lane * 4] = av;
    if (lane == 0) {
        g_dis[w] = rsqrtf(deg);
        float z = g_zsum[w] / fmaxf((float)c, 1.0f);
        out_rep[(size_t)w * DDIM + 256] = z;
        y0[w] = b01[0];
        y1[w] = b11[0];
    }
}

// ---------- kernel 4: edge aggregation (one warp per edge, fp32 atomics) ----------
__global__ __launch_bounds__(256) void k_edgeagg(const int* __restrict__ ei)
{
    int gw = (blockIdx.x * 256 + threadIdx.x) >> 5;
    int lane = threadIdx.x & 31;
    if (gw >= EE) return;
    int s = ei[gw];
    int d = ei[EE + gw];
    float coef = g_dis[s] * g_dis[d];
    float4 hv = *(const float4*)&g_h[(size_t)s * GDIM + lane * 4];
    float* ap = &g_agg[(size_t)d * GDIM + lane * 4];
    atomicAdd(ap + 0, hv.x * coef);
    atomicAdd(ap + 1, hv.y * coef);
    atomicAdd(ap + 2, hv.z * coef);
    atomicAdd(ap + 3, hv.w * coef);
}

// ---------- kernel 5: rep_gnn = relu(agg + b_gcn) -> rep cols [128,256) ----------
__global__ void k_assemble(const float* __restrict__ bgcn, float* __restrict__ out_rep)
{
    int w = (blockIdx.x * blockDim.x + threadIdx.x) >> 5;
    int lane = threadIdx.x & 31;
    if (w >= NN) return;
    float4 av = *(const float4*)&g_agg[(size_t)w * GDIM + lane * 4];
    int cb = lane * 4;
    float* o = &out_rep[(size_t)w * DDIM + 128];
    o[cb + 0] = fmaxf(av.x + bgcn[cb + 0], 0.f);
    o[cb + 1] = fmaxf(av.y + bgcn[cb + 1], 0.f);
    o[cb + 2] = fmaxf(av.z + bgcn[cb + 2], 0.f);
    o[cb + 3] = fmaxf(av.w + bgcn[cb + 3], 0.f);
}

// ---------- kernel 6: head GEMMs + fused projection to y0/y1 ----------
// y = relu(rep @ W + b) @ Wv, accumulated via atomicAdd (y pre-init to bias)
__global__ __launch_bounds__(256) void k_head(
    const float* __restrict__ rep,
    const float* __restrict__ W00, const float* __restrict__ b00,
    const float* __restrict__ W10, const float* __restrict__ b10,
    const float* __restrict__ W01, const float* __restrict__ W11,
    float* __restrict__ y0, float* __restrict__ y1)
{
    const float* W  = blockIdx.z ? W10 : W00;
    const float* b  = blockIdx.z ? b10 : b00;
    const float* Wv = blockIdx.z ? W11 : W01;
    float* yo       = blockIdx.z ? y1 : y0;

    __shared__ float sA[64 * 33];
    __shared__ float sW[32 * 65];

    const int row0 = blockIdx.x * 64;
    const int col0 = blockIdx.y * 64;
    const int t  = threadIdx.x;
    const int ty = t >> 4, tx = t & 15;
    const int r0 = ty * 4, c0 = tx * 4;

    float acc[4][4];
#pragma unroll
    for (int i = 0; i < 4; i++)
#pragma unroll
        for (int j = 0; j < 4; j++) acc[i][j] = 0.f;

    for (int k0 = 0; k0 < DDIM; k0 += 32) {
#pragma unroll
        for (int i = 0; i < 8; i++) {
            int idx = t + i * 256;
            int r = idx >> 5, kk = idx & 31;
            int grow = row0 + r, gk = k0 + kk;
            sA[r * 33 + kk] = (grow < NN && gk < DDIM)
                ? rep[(size_t)grow * DDIM + gk] : 0.f;
        }
#pragma unroll
        for (int i = 0; i < 8; i++) {
            int idx = t + i * 256;
            int kr = idx >> 6, c = idx & 63;
            int gk = k0 + kr, gc = col0 + c;
            sW[kr * 65 + c] = (gk < DDIM && gc < DDIM)
                ? W[(size_t)gk * DDIM + gc] : 0.f;
        }
        __syncthreads();
#pragma unroll
        for (int kk = 0; kk < 32; kk++) {
            float a[4], w[4];
#pragma unroll
            for (int i = 0; i < 4; i++) a[i] = sA[(r0 + i) * 33 + kk];
#pragma unroll
            for (int j = 0; j < 4; j++) w[j] = sW[kk * 65 + c0 + j];
#pragma unroll
            for (int i = 0; i < 4; i++)
#pragma unroll
                for (int j = 0; j < 4; j++) acc[i][j] = fmaf(a[i], w[j], acc[i][j]);
        }
        __syncthreads();
    }

    // epilogue: relu + bias, dot with Wv, reduce over the 16-lane tx group
    float part[4] = {0.f, 0.f, 0.f, 0.f};
#pragma unroll
    for (int j = 0; j < 4; j++) {
        int gc = col0 + c0 + j;
        if (gc < DDIM) {
            float bb = b[gc], wv = Wv[gc];
#pragma unroll
            for (int i = 0; i < 4; i++) {
                float v = acc[i][j] + bb;
                v = v > 0.f ? v : 0.f;
                part[i] = fmaf(v, wv, part[i]);
            }
        }
    }
#pragma unroll
    for (int off = 8; off >= 1; off >>= 1)
#pragma unroll
        for (int i = 0; i < 4; i++)
            part[i] += __shfl_xor_sync(0xffffffffu, part[i], off);
    if (tx == 0) {
#pragma unroll
        for (int i = 0; i < 4; i++) {
            int grow = row0 + r0 + i;
            if (grow < NN) atomicAdd(&yo[grow], part[i]);
        }
    }
}

// ---------- launch ----------
extern "C" void kernel_launch(void* const* d_in, const int* in_sizes, int n_in,
                              void* d_out, int out_size)
{
    const float* X    = (const float*)d_in[0];
    const float* T    = (const float*)d_in[1];
    const int*   ei   = (const int*)d_in[2];
    const float* Wphi = (const float*)d_in[3];
    const float* bphi = (const float*)d_in[4];
    const float* Wgcn = (const float*)d_in[5];
    const float* bgcn = (const float*)d_in[6];
    const float* W00  = (const float*)d_in[7];
    const float* b00  = (const float*)d_in[8];
    const float* W10  = (const float*)d_in[9];
    const float* b10  = (const float*)d_in[10];
    const float* W01  = (const float*)d_in[11];
    const float* b01  = (const float*)d_in[12];
    const float* W11  = (const float*)d_in[13];
    const float* b11  = (const float*)d_in[14];

    float* out = (float*)d_out;
    float* y0  = out;
    float* y1  = out + NN;
    float* rep = out + 2 * NN;

    k_zero<<<(NN + 255) / 256, 256>>>();
    k_phi<<<(NN + 63) / 64, 256>>>(X, T, Wphi, bphi, Wgcn, rep);
    k_edge1<<<(EE + 255) / 256, 256>>>(ei, T);
    k_node<<<(NN * 32 + 255) / 256, 256>>>(b01, b11, y0, y1, rep);
    k_edgeagg<<<(EE * 32 + 255) / 256, 256>>>(ei);
    k_assemble<<<(NN * 32 + 255) / 256, 256>>>(bgcn, rep);
    dim3 g((NN + 63) / 64, (DDIM + 63) / 64, 2);
    k_head<<<g, 256>>>(rep, W00, b00, W10, b10, W01, W11, y0, y1);
}

// round 3
// speedup vs baseline: 1.7776x; 1.7776x over previous
#include <cuda_runtime.h>

#define NN 100000
#define EE 3200000
#define XDIM 256
#define HDIM 128
#define GDIM 128
#define DDIM 257
#define NB 391   // ceil(NN/256)

// ---------- scratch (device globals; no allocation allowed) ----------
__device__ float g_h[(size_t)NN * HDIM];   // h = (T*phi) @ W_gcn
__device__ int   g_cnt[NN];                // in-degree (no self loop)
__device__ int   g_rowptr[NN + 1];         // CSR row pointers (by dst)
__device__ int   g_woff[NN];               // scatter write offsets
__device__ int   g_csr[EE];                // CSR: src ids grouped by dst
__device__ float g_dis[NN];                // rsqrt(deg)
__device__ int   g_blksum[512];            // per-block count sums for scan

// ---------- packed f32x2 FMA ----------
__device__ __forceinline__ void ffma2(unsigned long long& d,
                                      unsigned long long a,
                                      unsigned long long b)
{
    asm("fma.rn.f32x2 %0, %1, %2, %3;" : "=l"(d) : "l"(a), "l"(b), "l"(d));
}

// ---------- kernel 0: zero degree counters ----------
__global__ void k_zero()
{
    int i = blockIdx.x * blockDim.x + threadIdx.x;
    if (i < NN) g_cnt[i] = 0;
}

// ---------- kernel 1: fused phi = relu(X@Wphi+b) -> rep, h = (T*phi)@Wgcn ----------
__global__ __launch_bounds__(256) void k_phi(
    const float* __restrict__ X, const float* __restrict__ T,
    const float* __restrict__ Wphi, const float* __restrict__ bphi,
    const float* __restrict__ Wgcn, float* __restrict__ out_rep)
{
    __shared__ float smem[12288]; // 48KB
    float* sX = smem;             // [64][33]
    float* sW = smem + 64 * 33;   // [32][128]
    float* sP  = smem;            // [64][128]  (T-scaled phi)
    float* sWg = smem + 64 * 128; // [32][128]

    const int row0 = blockIdx.x * 64;
    const int t  = threadIdx.x;
    const int ty = t >> 4, tx = t & 15;
    const int r0 = ty * 4, c0 = tx * 8;

    float acc[4][8];
#pragma unroll
    for (int i = 0; i < 4; i++)
#pragma unroll
        for (int j = 0; j < 8; j++) acc[i][j] = 0.f;

    for (int k0 = 0; k0 < XDIM; k0 += 32) {
#pragma unroll
        for (int i = 0; i < 8; i++) {
            int idx = t + i * 256;
            int r = idx >> 5, kk = idx & 31;
            int grow = row0 + r;
            sX[r * 33 + kk] = (grow < NN) ? X[(size_t)grow * XDIM + k0 + kk] : 0.f;
        }
#pragma unroll
        for (int i = 0; i < 16; i++) {
            int idx = t + i * 256;
            int kr = idx >> 7, c = idx & 127;
            sW[kr * 128 + c] = Wphi[(size_t)(k0 + kr) * HDIM + c];
        }
        __syncthreads();
#pragma unroll
        for (int kk = 0; kk < 32; kk++) {
            float a[4], w[8];
#pragma unroll
            for (int i = 0; i < 4; i++) a[i] = sX[(r0 + i) * 33 + kk];
#pragma unroll
            for (int j = 0; j < 8; j++) w[j] = sW[kk * 128 + c0 + j];
#pragma unroll
            for (int i = 0; i < 4; i++)
#pragma unroll
                for (int j = 0; j < 8; j++) acc[i][j] = fmaf(a[i], w[j], acc[i][j]);
        }
        __syncthreads();
    }

    float tv[4];
#pragma unroll
    for (int i = 0; i < 4; i++) {
        int grow = row0 + r0 + i;
        tv[i] = (grow < NN) ? T[grow] : 0.f;
    }
#pragma unroll
    for (int i = 0; i < 4; i++) {
        int grow = row0 + r0 + i;
#pragma unroll
        for (int j = 0; j < 8; j++) {
            float p = acc[i][j] + bphi[c0 + j];
            p = p > 0.f ? p : 0.f;
            if (grow < NN) out_rep[(size_t)grow * DDIM + c0 + j] = p;
            sP[(r0 + i) * 128 + c0 + j] = p * tv[i];
            acc[i][j] = 0.f;
        }
    }
    __syncthreads();

    for (int k0 = 0; k0 < HDIM; k0 += 32) {
#pragma unroll
        for (int i = 0; i < 16; i++) {
            int idx = t + i * 256;
            int kr = idx >> 7, c = idx & 127;
            sWg[kr * 128 + c] = Wgcn[(size_t)(k0 + kr) * GDIM + c];
        }
        __syncthreads();
#pragma unroll
        for (int kk = 0; kk < 32; kk++) {
            float a[4], w[8];
#pragma unroll
            for (int i = 0; i < 4; i++) a[i] = sP[(r0 + i) * 128 + k0 + kk];
#pragma unroll
            for (int j = 0; j < 8; j++) w[j] = sWg[kk * 128 + c0 + j];
#pragma unroll
            for (int i = 0; i < 4; i++)
#pragma unroll
                for (int j = 0; j < 8; j++) acc[i][j] = fmaf(a[i], w[j], acc[i][j]);
        }
        __syncthreads();
    }
#pragma unroll
    for (int i = 0; i < 4; i++) {
        int grow = row0 + r0 + i;
        if (grow < NN)
#pragma unroll
            for (int j = 0; j < 8; j++)
                g_h[(size_t)grow * GDIM + c0 + j] = acc[i][j];
    }
}

// ---------- kernel 2: count in-degree per dst ----------
__global__ void k_edge1(const int* __restrict__ ei)
{
    int e = blockIdx.x * blockDim.x + threadIdx.x;
    if (e >= EE) return;
    atomicAdd(&g_cnt[ei[EE + e]], 1);
}

// ---------- scan step 1: per-block sums of g_cnt ----------
__global__ void k_blocksum()
{
    __shared__ int sm[8];
    int t = threadIdx.x;
    int i = blockIdx.x * 256 + t;
    int v = (i < NN) ? g_cnt[i] : 0;
#pragma unroll
    for (int off = 16; off >= 1; off >>= 1)
        v += __shfl_xor_sync(0xffffffffu, v, off);
    if ((t & 31) == 0) sm[t >> 5] = v;
    __syncthreads();
    if (t == 0) {
        int s = 0;
#pragma unroll
        for (int w = 0; w < 8; w++) s += sm[w];
        g_blksum[blockIdx.x] = s;
    }
}

// ---------- scan step 2: exclusive scan of block sums (1 block) ----------
__global__ void k_scanblk()
{
    __shared__ int s[512];
    int t = threadIdx.x;
    int v = (t < NB) ? g_blksum[t] : 0;
    s[t] = v;
    __syncthreads();
    for (int off = 1; off < 512; off <<= 1) {
        int x = (t >= off) ? s[t - off] : 0;
        __syncthreads();
        s[t] += x;
        __syncthreads();
    }
    if (t < NB) g_blksum[t] = s[t] - v; // exclusive
}

// ---------- scan step 3: rowptr + woff + dis + y bias-init ----------
__global__ void k_rowptr(const float* __restrict__ b01, const float* __restrict__ b11,
                         float* __restrict__ y0, float* __restrict__ y1)
{
    __shared__ int s[256];
    int t = threadIdx.x;
    int i = blockIdx.x * 256 + t;
    int v = (i < NN) ? g_cnt[i] : 0;
    s[t] = v;
    __syncthreads();
    for (int off = 1; off < 256; off <<= 1) {
        int x = (t >= off) ? s[t - off] : 0;
        __syncthreads();
        s[t] += x;
        __syncthreads();
    }
    int incl = s[t];
    int base = g_blksum[blockIdx.x];
    if (i < NN) {
        int e = base + incl - v;
        g_rowptr[i] = e;
        g_woff[i]   = e;
        g_dis[i]    = rsqrtf((float)v + 1.0f);
        y0[i] = b01[0];
        y1[i] = b11[0];
    }
    if (i == NN - 1) g_rowptr[NN] = base + incl;
}

// ---------- kernel: scatter src ids into CSR ----------
__global__ void k_scatter(const int* __restrict__ ei)
{
    int e = blockIdx.x * blockDim.x + threadIdx.x;
    if (e >= EE) return;
    int s = ei[e];
    int d = ei[EE + e];
    int pos = atomicAdd(&g_woff[d], 1);
    g_csr[pos] = s;
}

// ---------- kernel: warp-per-node gather: rep_gnn + z, no atomics ----------
__global__ __launch_bounds__(256) void k_gather(
    const float* __restrict__ T, const float* __restrict__ bgcn,
    float* __restrict__ rep)
{
    int w = (blockIdx.x * 256 + threadIdx.x) >> 5;
    int lane = threadIdx.x & 31;
    if (w >= NN) return;
    int start = g_rowptr[w];
    int end   = g_rowptr[w + 1];
    float disd = g_dis[w];

    float4 acc = make_float4(0.f, 0.f, 0.f, 0.f);
    float zs = 0.f;
    int i = start;
    for (; i + 1 < end; i += 2) {
        int s0 = g_csr[i];
        int s1 = g_csr[i + 1];
        float cf0 = g_dis[s0] * disd;
        float cf1 = g_dis[s1] * disd;
        float4 h0 = *(const float4*)&g_h[(size_t)s0 * GDIM + lane * 4];
        float4 h1 = *(const float4*)&g_h[(size_t)s1 * GDIM + lane * 4];
        acc.x = fmaf(cf0, h0.x, acc.x); acc.x = fmaf(cf1, h1.x, acc.x);
        acc.y = fmaf(cf0, h0.y, acc.y); acc.y = fmaf(cf1, h1.y, acc.y);
        acc.z = fmaf(cf0, h0.z, acc.z); acc.z = fmaf(cf1, h1.z, acc.z);
        acc.w = fmaf(cf0, h0.w, acc.w); acc.w = fmaf(cf1, h1.w, acc.w);
        zs += T[s0] + T[s1];
    }
    if (i < end) {
        int s0 = g_csr[i];
        float cf0 = g_dis[s0] * disd;
        float4 h0 = *(const float4*)&g_h[(size_t)s0 * GDIM + lane * 4];
        acc.x = fmaf(cf0, h0.x, acc.x);
        acc.y = fmaf(cf0, h0.y, acc.y);
        acc.z = fmaf(cf0, h0.z, acc.z);
        acc.w = fmaf(cf0, h0.w, acc.w);
        zs += T[s0];
    }

    int cnt = end - start;
    float invd = 1.0f / ((float)cnt + 1.0f);
    float4 hd = *(const float4*)&g_h[(size_t)w * GDIM + lane * 4];
    int cb = lane * 4;
    float* o = &rep[(size_t)w * DDIM + 128 + cb];
    o[0] = fmaxf(fmaf(hd.x, invd, acc.x) + bgcn[cb + 0], 0.f);
    o[1] = fmaxf(fmaf(hd.y, invd, acc.y) + bgcn[cb + 1], 0.f);
    o[2] = fmaxf(fmaf(hd.z, invd, acc.z) + bgcn[cb + 2], 0.f);
    o[3] = fmaxf(fmaf(hd.w, invd, acc.w) + bgcn[cb + 3], 0.f);
    if (lane == 0)
        rep[(size_t)w * DDIM + 256] = zs / fmaxf((float)cnt, 1.0f);
}

// ---------- kernel: head GEMMs with packed f32x2 FMA ----------
// tile 256x64, microtile 16 rows x 4 cols, accumulators = row-pairs
__global__ __launch_bounds__(256, 2) void k_head(
    const float* __restrict__ rep,
    const float* __restrict__ W00, const float* __restrict__ b00,
    const float* __restrict__ W10, const float* __restrict__ b10,
    const float* __restrict__ W01, const float* __restrict__ W11,
    float* __restrict__ y0, float* __restrict__ y1)
{
    const float* W  = blockIdx.z ? W10 : W00;
    const float* b  = blockIdx.z ? b10 : b00;
    const float* Wv = blockIdx.z ? W11 : W01;
    float* yo       = blockIdx.z ? y1 : y0;

    __shared__ float sAT[32 * 258]; // A transposed: [kk][row], stride 258
    __shared__ float sW[32 * 68];   // [kk][col]

    const int row0 = blockIdx.x * 256;
    const int col0 = blockIdx.y * 64;
    const int t  = threadIdx.x;
    const int r0 = (t >> 4) * 16;
    const int c0 = (t & 15) * 4;

    unsigned long long acc2[8][4];
#pragma unroll
    for (int p = 0; p < 8; p++)
#pragma unroll
        for (int j = 0; j < 4; j++) acc2[p][j] = 0ull;

    for (int k0 = 0; k0 < DDIM; k0 += 32) {
        bool fast = (row0 + 256 <= NN) && (k0 + 32 <= DDIM);
        if (fast) {
#pragma unroll
            for (int it = 0; it < 32; it++) {
                int q = t + it * 256;
                int r = q >> 5, kk = q & 31;
                sAT[kk * 258 + r] = rep[(size_t)(row0 + r) * DDIM + k0 + kk];
            }
        } else {
#pragma unroll
            for (int it = 0; it < 32; it++) {
                int q = t + it * 256;
                int r = q >> 5, kk = q & 31;
                int grow = row0 + r, gk = k0 + kk;
                sAT[kk * 258 + r] = (grow < NN && gk < DDIM)
                    ? rep[(size_t)grow * DDIM + gk] : 0.f;
            }
        }
#pragma unroll
        for (int it = 0; it < 8; it++) {
            int q = t + it * 256;
            int kr = q >> 6, c = q & 63;
            int gk = k0 + kr, gc = col0 + c;
            sW[kr * 68 + c] = (gk < DDIM && gc < DDIM)
                ? W[(size_t)gk * DDIM + gc] : 0.f;
        }
        __syncthreads();
#pragma unroll
        for (int kk = 0; kk < 32; kk++) {
            unsigned long long a2[8];
#pragma unroll
            for (int p = 0; p < 8; p++)
                a2[p] = *(const unsigned long long*)&sAT[kk * 258 + r0 + 2 * p];
            unsigned long long w2[4];
#pragma unroll
            for (int j = 0; j < 4; j++) {
                float wv = sW[kk * 68 + c0 + j];
                asm("mov.b64 %0, {%1, %1};" : "=l"(w2[j]) : "f"(wv));
            }
#pragma unroll
            for (int p = 0; p < 8; p++)
#pragma unroll
                for (int j = 0; j < 4; j++)
                    ffma2(acc2[p][j], a2[p], w2[j]);
        }
        __syncthreads();
    }

    // epilogue: relu(acc+b) dot Wv, reduce across the 16 tx lanes
    float part[16];
#pragma unroll
    for (int i = 0; i < 16; i++) part[i] = 0.f;
#pragma unroll
    for (int j = 0; j < 4; j++) {
        int gc = col0 + c0 + j;
        float bb = (gc < DDIM) ? b[gc] : 0.f;
        float wv = (gc < DDIM) ? Wv[gc] : 0.f;
#pragma unroll
        for (int p = 0; p < 8; p++) {
            union { unsigned long long u; float2 f; } cv;
            cv.u = acc2[p][j];
            float v0 = fmaxf(cv.f.x + bb, 0.f);
            float v1 = fmaxf(cv.f.y + bb, 0.f);
            part[2 * p]     = fmaf(v0, wv, part[2 * p]);
            part[2 * p + 1] = fmaf(v1, wv, part[2 * p + 1]);
        }
    }
#pragma unroll
    for (int off = 8; off >= 1; off >>= 1)
#pragma unroll
        for (int i = 0; i < 16; i++)
            part[i] += __shfl_xor_sync(0xffffffffu, part[i], off);
    if ((t & 15) == 0) {
#pragma unroll
        for (int i = 0; i < 16; i++) {
            int grow = row0 + r0 + i;
            if (grow < NN) atomicAdd(&yo[grow], part[i]);
        }
    }
}

// ---------- launch ----------
extern "C" void kernel_launch(void* const* d_in, const int* in_sizes, int n_in,
                              void* d_out, int out_size)
{
    const float* X    = (const float*)d_in[0];
    const float* T    = (const float*)d_in[1];
    const int*   ei   = (const int*)d_in[2];
    const float* Wphi = (const float*)d_in[3];
    const float* bphi = (const float*)d_in[4];
    const float* Wgcn = (const float*)d_in[5];
    const float* bgcn = (const float*)d_in[6];
    const float* W00  = (const float*)d_in[7];
    const float* b00  = (const float*)d_in[8];
    const float* W10  = (const float*)d_in[9];
    const float* b10  = (const float*)d_in[10];
    const float* W01  = (const float*)d_in[11];
    const float* b01  = (const float*)d_in[12];
    const float* W11  = (const float*)d_in[13];
    const float* b11  = (const float*)d_in[14];

    float* out = (float*)d_out;
    float* y0  = out;
    float* y1  = out + NN;
    float* rep = out + 2 * NN;

    k_zero<<<NB, 256>>>();
    k_phi<<<(NN + 63) / 64, 256>>>(X, T, Wphi, bphi, Wgcn, rep);
    k_edge1<<<(EE + 255) / 256, 256>>>(ei);
    k_blocksum<<<NB, 256>>>();
    k_scanblk<<<1, 512>>>();
    k_rowptr<<<NB, 256>>>(b01, b11, y0, y1);
    k_scatter<<<(EE + 255) / 256, 256>>>(ei);
    k_gather<<<(NN * 32 + 255) / 256, 256>>>(T, bgcn, rep);
    dim3 g((NN + 255) / 256, (DDIM + 63) / 64, 2);
    k_head<<<g, 256>>>(rep, W00, b00, W10, b10, W01, W11, y0, y1);
}

// round 6
// speedup vs baseline: 2.6223x; 1.4752x over previous
#include <cuda_runtime.h>
#include <cuda_bf16.h>
#include <cstdint>

#define NN 100000
#define EE 3200000
#define XDIM 256
#define HDIM 128
#define GDIM 128
#define DDIM 257
#define NB 391        // ceil(NN/256)
#define KPAD 288      // padded K for head GEMM (9 x 32)
#define NPAD 320      // padded N (5 x 64)
#define KCH 9

// ---------- scratch (device globals; no allocation allowed) ----------
__device__ float g_h[(size_t)NN * HDIM];
__device__ int   g_cnt[NN];
__device__ int   g_rowptr[NN + 1];
__device__ int   g_woff[NN];
__device__ int   g_csr[EE];
__device__ float g_dis[NN];
__device__ int   g_blksum[512];
__device__ __nv_bfloat16 g_rep_hi[(size_t)NN * KPAD];
__device__ __nv_bfloat16 g_rep_lo[(size_t)NN * KPAD];
__device__ __nv_bfloat16 g_wt[2][2][NPAD * KPAD];   // [head][hi/lo][n*KPAD+k]

// ---------- helpers ----------
__device__ __forceinline__ uint32_t smem_u32(const void* p) {
    uint32_t a;
    asm("{ .reg .u64 t; cvta.to.shared.u64 t, %1; cvt.u32.u64 %0, t; }"
        : "=r"(a) : "l"(p));
    return a;
}
__device__ __forceinline__ void ffma2(unsigned long long& d,
                                      unsigned long long a,
                                      unsigned long long b)
{
    asm("fma.rn.f32x2 %0, %1, %2, %3;" : "=l"(d) : "l"(a), "l"(b), "l"(d));
}
__device__ __forceinline__ void ldm_x4(uint32_t& r0, uint32_t& r1,
                                       uint32_t& r2, uint32_t& r3, uint32_t addr)
{
    asm volatile("ldmatrix.sync.aligned.m8n8.x4.shared.b16 {%0,%1,%2,%3}, [%4];"
        : "=r"(r0), "=r"(r1), "=r"(r2), "=r"(r3) : "r"(addr));
}
__device__ __forceinline__ void mma_bf16(float* c, const uint32_t* a,
                                         uint32_t b0, uint32_t b1)
{
    asm volatile("mma.sync.aligned.m16n8k16.row.col.f32.bf16.bf16.f32 "
        "{%0,%1,%2,%3}, {%4,%5,%6,%7}, {%8,%9}, {%0,%1,%2,%3};"
        : "+f"(c[0]), "+f"(c[1]), "+f"(c[2]), "+f"(c[3])
        : "r"(a[0]), "r"(a[1]), "r"(a[2]), "r"(a[3]), "r"(b0), "r"(b1));
}

// ---------- kernel 0: zero degree counters ----------
__global__ void k_zero()
{
    int i = blockIdx.x * blockDim.x + threadIdx.x;
    if (i < NN) g_cnt[i] = 0;
}

// ---------- kernel 1: fused phi (FFMA2) ----------
// tile 128 rows x 128 cols, microtile 16 rows (8 pairs) x 4 cols
#define PHI_SMEM 83456
__global__ __launch_bounds__(256) void k_phi(
    const float* __restrict__ X, const float* __restrict__ T,
    const float* __restrict__ Wphi, const float* __restrict__ bphi,
    const float* __restrict__ Wgcn, float* __restrict__ out_rep)
{
    extern __shared__ float psm[];
    float* sXT = psm;             // [32][130]  phase1 A^T
    float* sW  = psm + 4160;      // [32][132]  phase1 W
    float* sPT = psm;             // [128][130] phase2 (T*phi)^T
    float* sWg = psm + 16640;     // [32][132]  phase2 W

    const int row0 = blockIdx.x * 128;
    const int t  = threadIdx.x;
    const int r0 = (t >> 5) * 16;
    const int c0 = (t & 31) * 4;

    unsigned long long acc2[8][4];
#pragma unroll
    for (int p = 0; p < 8; p++)
#pragma unroll
        for (int j = 0; j < 4; j++) acc2[p][j] = 0ull;

    // ---- phase 1: phi = X @ Wphi (K = 256) ----
    for (int k0 = 0; k0 < XDIM; k0 += 32) {
#pragma unroll
        for (int it = 0; it < 16; it++) {
            int q = t + it * 256;
            int r = q >> 5, kk = q & 31;
            int grow = row0 + r;
            sXT[kk * 130 + r] = (grow < NN) ? X[(size_t)grow * XDIM + k0 + kk] : 0.f;
        }
#pragma unroll
        for (int it = 0; it < 16; it++) {
            int q = t + it * 256;
            int kr = q >> 7, c = q & 127;
            sW[kr * 132 + c] = Wphi[(size_t)(k0 + kr) * HDIM + c];
        }
        __syncthreads();
#pragma unroll
        for (int kk = 0; kk < 32; kk++) {
            unsigned long long a2[8];
#pragma unroll
            for (int p = 0; p < 8; p++)
                a2[p] = *(const unsigned long long*)&sXT[kk * 130 + r0 + 2 * p];
            float4 w4 = *(const float4*)&sW[kk * 132 + c0];
            unsigned long long w2[4];
            asm("mov.b64 %0, {%1, %1};" : "=l"(w2[0]) : "f"(w4.x));
            asm("mov.b64 %0, {%1, %1};" : "=l"(w2[1]) : "f"(w4.y));
            asm("mov.b64 %0, {%1, %1};" : "=l"(w2[2]) : "f"(w4.z));
            asm("mov.b64 %0, {%1, %1};" : "=l"(w2[3]) : "f"(w4.w));
#pragma unroll
            for (int p = 0; p < 8; p++)
#pragma unroll
                for (int j = 0; j < 4; j++)
                    ffma2(acc2[p][j], a2[p], w2[j]);
        }
        __syncthreads();
    }

    // ---- epilogue 1: relu+bias -> rep; T*phi -> sPT (transposed) ----
#pragma unroll
    for (int p = 0; p < 8; p++) {
        int rA = r0 + 2 * p, rB = rA + 1;
        int gA = row0 + rA, gB = row0 + rB;
        float tA = (gA < NN) ? T[gA] : 0.f;
        float tB = (gB < NN) ? T[gB] : 0.f;
#pragma unroll
        for (int j = 0; j < 4; j++) {
            union { unsigned long long u; float2 f; } cv;
            cv.u = acc2[p][j];
            int c = c0 + j;
            float bb = bphi[c];
            float pA = fmaxf(cv.f.x + bb, 0.f);
            float pB = fmaxf(cv.f.y + bb, 0.f);
            if (gA < NN) out_rep[(size_t)gA * DDIM + c] = pA;
            if (gB < NN) out_rep[(size_t)gB * DDIM + c] = pB;
            sPT[c * 130 + rA] = pA * tA;
            sPT[c * 130 + rB] = pB * tB;
            acc2[p][j] = 0ull;
        }
    }
    __syncthreads();

    // ---- phase 2: h = (T*phi) @ Wgcn (K = 128) ----
    for (int k0 = 0; k0 < HDIM; k0 += 32) {
#pragma unroll
        for (int it = 0; it < 16; it++) {
            int q = t + it * 256;
            int kr = q >> 7, c = q & 127;
            sWg[kr * 132 + c] = Wgcn[(size_t)(k0 + kr) * GDIM + c];
        }
        __syncthreads();
#pragma unroll
        for (int kk = 0; kk < 32; kk++) {
            unsigned long long a2[8];
#pragma unroll
            for (int p = 0; p < 8; p++)
                a2[p] = *(const unsigned long long*)&sPT[(k0 + kk) * 130 + r0 + 2 * p];
            float4 w4 = *(const float4*)&sWg[kk * 132 + c0];
            unsigned long long w2[4];
            asm("mov.b64 %0, {%1, %1};" : "=l"(w2[0]) : "f"(w4.x));
            asm("mov.b64 %0, {%1, %1};" : "=l"(w2[1]) : "f"(w4.y));
            asm("mov.b64 %0, {%1, %1};" : "=l"(w2[2]) : "f"(w4.z));
            asm("mov.b64 %0, {%1, %1};" : "=l"(w2[3]) : "f"(w4.w));
#pragma unroll
            for (int p = 0; p < 8; p++)
#pragma unroll
                for (int j = 0; j < 4; j++)
                    ffma2(acc2[p][j], a2[p], w2[j]);
        }
        __syncthreads();
    }

#pragma unroll
    for (int p = 0; p < 8; p++) {
        int gA = row0 + r0 + 2 * p, gB = gA + 1;
#pragma unroll
        for (int j = 0; j < 4; j++) {
            union { unsigned long long u; float2 f; } cv;
            cv.u = acc2[p][j];
            int c = c0 + j;
            if (gA < NN) g_h[(size_t)gA * GDIM + c] = cv.f.x;
            if (gB < NN) g_h[(size_t)gB * GDIM + c] = cv.f.y;
        }
    }
}

// ---------- count in-degree ----------
__global__ void k_edge1(const int* __restrict__ ei)
{
    int e = blockIdx.x * blockDim.x + threadIdx.x;
    if (e >= EE) return;
    atomicAdd(&g_cnt[ei[EE + e]], 1);
}

// ---------- scan step 1 ----------
__global__ void k_blocksum()
{
    __shared__ int sm[8];
    int t = threadIdx.x;
    int i = blockIdx.x * 256 + t;
    int v = (i < NN) ? g_cnt[i] : 0;
#pragma unroll
    for (int off = 16; off >= 1; off >>= 1)
        v += __shfl_xor_sync(0xffffffffu, v, off);
    if ((t & 31) == 0) sm[t >> 5] = v;
    __syncthreads();
    if (t == 0) {
        int s = 0;
#pragma unroll
        for (int w = 0; w < 8; w++) s += sm[w];
        g_blksum[blockIdx.x] = s;
    }
}

// ---------- scan step 2 ----------
__global__ void k_scanblk()
{
    __shared__ int s[512];
    int t = threadIdx.x;
    int v = (t < NB) ? g_blksum[t] : 0;
    s[t] = v;
    __syncthreads();
    for (int off = 1; off < 512; off <<= 1) {
        int x = (t >= off) ? s[t - off] : 0;
        __syncthreads();
        s[t] += x;
        __syncthreads();
    }
    if (t < NB) g_blksum[t] = s[t] - v;
}

// ---------- scan step 3: rowptr + woff + dis + y bias init ----------
__global__ void k_rowptr(const float* __restrict__ b01, const float* __restrict__ b11,
                         float* __restrict__ y0, float* __restrict__ y1)
{
    __shared__ int s[256];
    int t = threadIdx.x;
    int i = blockIdx.x * 256 + t;
    int v = (i < NN) ? g_cnt[i] : 0;
    s[t] = v;
    __syncthreads();
    for (int off = 1; off < 256; off <<= 1) {
        int x = (t >= off) ? s[t - off] : 0;
        __syncthreads();
        s[t] += x;
        __syncthreads();
    }
    int incl = s[t];
    int base = g_blksum[blockIdx.x];
    if (i < NN) {
        int e = base + incl - v;
        g_rowptr[i] = e;
        g_woff[i]   = e;
        g_dis[i]    = rsqrtf((float)v + 1.0f);
        y0[i] = b01[0];
        y1[i] = b11[0];
    }
    if (i == NN - 1) g_rowptr[NN] = base + incl;
}

// ---------- scatter into CSR ----------
__global__ void k_scatter(const int* __restrict__ ei)
{
    int e = blockIdx.x * blockDim.x + threadIdx.x;
    if (e >= EE) return;
    int s = ei[e];
    int d = ei[EE + e];
    int pos = atomicAdd(&g_woff[d], 1);
    g_csr[pos] = s;
}

// ---------- warp-per-node gather: rep_gnn + z ----------
__global__ __launch_bounds__(256) void k_gather(
    const float* __restrict__ T, const float* __restrict__ bgcn,
    float* __restrict__ rep)
{
    int w = (blockIdx.x * 256 + threadIdx.x) >> 5;
    int lane = threadIdx.x & 31;
    if (w >= NN) return;
    int start = g_rowptr[w];
    int end   = g_rowptr[w + 1];
    float disd = g_dis[w];

    float4 acc = make_float4(0.f, 0.f, 0.f, 0.f);
    float zs = 0.f;
    int i = start;
    for (; i + 1 < end; i += 2) {
        int s0 = g_csr[i];
        int s1 = g_csr[i + 1];
        float cf0 = g_dis[s0] * disd;
        float cf1 = g_dis[s1] * disd;
        float4 h0 = *(const float4*)&g_h[(size_t)s0 * GDIM + lane * 4];
        float4 h1 = *(const float4*)&g_h[(size_t)s1 * GDIM + lane * 4];
        acc.x = fmaf(cf0, h0.x, acc.x); acc.x = fmaf(cf1, h1.x, acc.x);
        acc.y = fmaf(cf0, h0.y, acc.y); acc.y = fmaf(cf1, h1.y, acc.y);
        acc.z = fmaf(cf0, h0.z, acc.z); acc.z = fmaf(cf1, h1.z, acc.z);
        acc.w = fmaf(cf0, h0.w, acc.w); acc.w = fmaf(cf1, h1.w, acc.w);
        zs += T[s0] + T[s1];
    }
    if (i < end) {
        int s0 = g_csr[i];
        float cf0 = g_dis[s0] * disd;
        float4 h0 = *(const float4*)&g_h[(size_t)s0 * GDIM + lane * 4];
        acc.x = fmaf(cf0, h0.x, acc.x);
        acc.y = fmaf(cf0, h0.y, acc.y);
        acc.z = fmaf(cf0, h0.z, acc.z);
        acc.w = fmaf(cf0, h0.w, acc.w);
        zs += T[s0];
    }

    int cnt = end - start;
    float invd = 1.0f / ((float)cnt + 1.0f);
    float4 hd = *(const float4*)&g_h[(size_t)w * GDIM + lane * 4];
    int cb = lane * 4;
    float* o = &rep[(size_t)w * DDIM + 128 + cb];
    o[0] = fmaxf(fmaf(hd.x, invd, acc.x) + bgcn[cb + 0], 0.f);
    o[1] = fmaxf(fmaf(hd.y, invd, acc.y) + bgcn[cb + 1], 0.f);
    o[2] = fmaxf(fmaf(hd.z, invd, acc.z) + bgcn[cb + 2], 0.f);
    o[3] = fmaxf(fmaf(hd.w, invd, acc.w) + bgcn[cb + 3], 0.f);
    if (lane == 0)
        rep[(size_t)w * DDIM + 256] = zs / fmaxf((float)cnt, 1.0f);
}

// ---------- bf16 split of rep (K padded to 288) ----------
__global__ void k_cvt_rep(const float* __restrict__ rep)
{
    int idx = blockIdx.x * 256 + threadIdx.x;
    if (idx >= NN * KPAD) return;
    int r = idx / KPAD, k = idx - r * KPAD;
    float x = (k < DDIM) ? rep[(size_t)r * DDIM + k] : 0.f;
    __nv_bfloat16 hi = __float2bfloat16(x);
    float res = x - __bfloat162float(hi);
    g_rep_hi[idx] = hi;
    g_rep_lo[idx] = __float2bfloat16(res);
}

// ---------- bf16 split of W00/W10 transposed ----------
__global__ void k_cvt_w(const float* __restrict__ W00, const float* __restrict__ W10)
{
    int idx = blockIdx.x * 256 + threadIdx.x;
    if (idx >= 2 * NPAD * KPAD) return;
    int head = idx / (NPAD * KPAD);
    int rem = idx - head * (NPAD * KPAD);
    int n = rem / KPAD, k = rem - n * KPAD;
    const float* W = head ? W10 : W00;
    float x = (n < DDIM && k < DDIM) ? W[(size_t)k * DDIM + n] : 0.f;
    __nv_bfloat16 hi = __float2bfloat16(x);
    float res = x - __bfloat162float(hi);
    g_wt[head][0][rem] = hi;
    g_wt[head][1][rem] = __float2bfloat16(res);
}

// ---------- head GEMM via mma.sync bf16 (3-pass hi/lo) ----------
// CTA tile 128x64, warp tile 32x32, k-chunks of 32 in smem (80B pitch)
#define HEAD_SMEM 30720
__global__ __launch_bounds__(256) void k_head_mma(
    const float* __restrict__ b00, const float* __restrict__ b10,
    const float* __restrict__ W01, const float* __restrict__ W11,
    float* __restrict__ y0, float* __restrict__ y1)
{
    extern __shared__ char hsm[];
    // A_hi @0 (10240B), A_lo @10240, B_hi @20480 (5120B), B_lo @25600
    uint32_t sb = smem_u32(hsm);
    const int tid = threadIdx.x, lane = tid & 31, wid = tid >> 5;
    const int wm = wid & 3, wn = wid >> 2;
    const int head = blockIdx.z;
    const int row0 = blockIdx.x * 128;
    const int col0 = blockIdx.y * 64;
    const float* bptr = head ? b10 : b00;
    const float* wv   = head ? W11 : W01;
    float* yo = head ? y1 : y0;
    const __nv_bfloat16* whi = g_wt[head][0];
    const __nv_bfloat16* wlo = g_wt[head][1];

    float acc[2][4][4];
#pragma unroll
    for (int mt = 0; mt < 2; mt++)
#pragma unroll
        for (int nt = 0; nt < 4; nt++)
#pragma unroll
            for (int j = 0; j < 4; j++) acc[mt][nt][j] = 0.f;

    for (int kc = 0; kc < KCH; kc++) {
        int kbase = kc * 32;
        // A: 128 rows x 32 bf16 per half
#pragma unroll
        for (int it = 0; it < 2; it++) {
            int q = tid + it * 256;
            int r = q >> 2, v = q & 3;
            int grow = row0 + r;
            uint4 vh = make_uint4(0, 0, 0, 0), vl = vh;
            if (grow < NN) {
                vh = *(const uint4*)&g_rep_hi[(size_t)grow * KPAD + kbase + v * 8];
                vl = *(const uint4*)&g_rep_lo[(size_t)grow * KPAD + kbase + v * 8];
            }
            *(uint4*)(hsm + r * 80 + v * 16) = vh;
            *(uint4*)(hsm + 10240 + r * 80 + v * 16) = vl;
        }
        // B: 64 n-rows x 32 bf16 per half
        {
            int n = tid >> 2, v = tid & 3;
            uint4 vh = *(const uint4*)&whi[(size_t)(col0 + n) * KPAD + kbase + v * 8];
            uint4 vl = *(const uint4*)&wlo[(size_t)(col0 + n) * KPAD + kbase + v * 8];
            *(uint4*)(hsm + 20480 + n * 80 + v * 16) = vh;
            *(uint4*)(hsm + 25600 + n * 80 + v * 16) = vl;
        }
        __syncthreads();

#pragma unroll
        for (int ks = 0; ks < 2; ks++) {
            uint32_t ahi[2][4], alo[2][4], bhi[4][2], blo[4][2];
#pragma unroll
            for (int mt = 0; mt < 2; mt++) {
                uint32_t ad = sb + (wm * 32 + mt * 16 + (lane & 15)) * 80
                            + ((lane >> 4) & 1) * 16 + ks * 32;
                ldm_x4(ahi[mt][0], ahi[mt][1], ahi[mt][2], ahi[mt][3], ad);
                ldm_x4(alo[mt][0], alo[mt][1], alo[mt][2], alo[mt][3], ad + 10240);
            }
#pragma unroll
            for (int g2 = 0; g2 < 2; g2++) {
                uint32_t bd = sb + 20480
                            + (wn * 32 + g2 * 16 + (lane & 7) + ((lane >> 4) & 1) * 8) * 80
                            + ((lane >> 3) & 1) * 16 + ks * 32;
                ldm_x4(bhi[2 * g2][0], bhi[2 * g2][1], bhi[2 * g2 + 1][0], bhi[2 * g2 + 1][1], bd);
                ldm_x4(blo[2 * g2][0], blo[2 * g2][1], blo[2 * g2 + 1][0], blo[2 * g2 + 1][1], bd + 5120);
            }
#pragma unroll
            for (int mt = 0; mt < 2; mt++)
#pragma unroll
                for (int nt = 0; nt < 4; nt++) {
                    mma_bf16(acc[mt][nt], ahi[mt], bhi[nt][0], bhi[nt][1]);
                    mma_bf16(acc[mt][nt], ahi[mt], blo[nt][0], blo[nt][1]);
                    mma_bf16(acc[mt][nt], alo[mt], bhi[nt][0], bhi[nt][1]);
                }
        }
        __syncthreads();
    }

    // epilogue: relu(acc+bias) dot Wv -> per-row partials -> atomicAdd
    float pr[2][2] = {{0.f, 0.f}, {0.f, 0.f}};
#pragma unroll
    for (int nt = 0; nt < 4; nt++) {
        int gc0 = col0 + wn * 32 + nt * 8 + 2 * (lane & 3);
        int gc1 = gc0 + 1;
        float bb0 = (gc0 < DDIM) ? bptr[gc0] : 0.f;
        float wv0 = (gc0 < DDIM) ? wv[gc0] : 0.f;
        float bb1 = (gc1 < DDIM) ? bptr[gc1] : 0.f;
        float wv1 = (gc1 < DDIM) ? wv[gc1] : 0.f;
#pragma unroll
        for (int mt = 0; mt < 2; mt++) {
            pr[mt][0] = fmaf(fmaxf(acc[mt][nt][0] + bb0, 0.f), wv0, pr[mt][0]);
            pr[mt][0] = fmaf(fmaxf(acc[mt][nt][1] + bb1, 0.f), wv1, pr[mt][0]);
            pr[mt][1] = fmaf(fmaxf(acc[mt][nt][2] + bb0, 0.f), wv0, pr[mt][1]);
            pr[mt][1] = fmaf(fmaxf(acc[mt][nt][3] + bb1, 0.f), wv1, pr[mt][1]);
        }
    }
#pragma unroll
    for (int off = 1; off <= 2; off <<= 1) {
#pragma unroll
        for (int mt = 0; mt < 2; mt++) {
            pr[mt][0] += __shfl_xor_sync(0xffffffffu, pr[mt][0], off);
            pr[mt][1] += __shfl_xor_sync(0xffffffffu, pr[mt][1], off);
        }
    }
    if ((lane & 3) == 0) {
        int rbase = row0 + wm * 32 + (lane >> 2);
#pragma unroll
        for (int mt = 0; mt < 2; mt++)
#pragma unroll
            for (int h = 0; h < 2; h++) {
                int grow = rbase + mt * 16 + h * 8;
                if (grow < NN) atomicAdd(&yo[grow], pr[mt][h]);
            }
    }
}

// ---------- launch ----------
extern "C" void kernel_launch(void* const* d_in, const int* in_sizes, int n_in,
                              void* d_out, int out_size)
{
    const float* X    = (const float*)d_in[0];
    const float* T    = (const float*)d_in[1];
    const int*   ei   = (const int*)d_in[2];
    const float* Wphi = (const float*)d_in[3];
    const float* bphi = (const float*)d_in[4];
    const float* Wgcn = (const float*)d_in[5];
    const float* bgcn = (const float*)d_in[6];
    const float* W00  = (const float*)d_in[7];
    const float* b00  = (const float*)d_in[8];
    const float* W10  = (const float*)d_in[9];
    const float* b10  = (const float*)d_in[10];
    const float* W01  = (const float*)d_in[11];
    const float* b01  = (const float*)d_in[12];
    const float* W11  = (const float*)d_in[13];
    const float* b11  = (const float*)d_in[14];

    float* out = (float*)d_out;
    float* y0  = out;
    float* y1  = out + NN;
    float* rep = out + 2 * NN;

    cudaFuncSetAttribute(k_phi, cudaFuncAttributeMaxDynamicSharedMemorySize, PHI_SMEM);
    cudaFuncSetAttribute(k_head_mma, cudaFuncAttributeMaxDynamicSharedMemorySize, HEAD_SMEM);

    k_zero<<<NB, 256>>>();
    k_cvt_w<<<(2 * NPAD * KPAD + 255) / 256, 256>>>(W00, W10);
    k_phi<<<(NN + 127) / 128, 256, PHI_SMEM>>>(X, T, Wphi, bphi, Wgcn, rep);
    k_edge1<<<(EE + 255) / 256, 256>>>(ei);
    k_blocksum<<<NB, 256>>>();
    k_scanblk<<<1, 512>>>();
    k_rowptr<<<NB, 256>>>(b01, b11, y0, y1);
    k_scatter<<<(EE + 255) / 256, 256>>>(ei);
    k_gather<<<(NN * 32 + 255) / 256, 256>>>(T, bgcn, rep);
    k_cvt_rep<<<(NN * KPAD + 255) / 256, 256>>>(rep);
    dim3 gh((NN + 127) / 128, 5, 2);
    k_head_mma<<<gh, 256, HEAD_SMEM>>>(b00, b10, W01, W11, y0, y1);
}